// round 15
// baseline (speedup 1.0000x reference)
#include <cuda_runtime.h>
#include <cuda_bf16.h>
#include <math.h>
#include <stdint.h>

// Problem constants
#define NB  2
#define NS  2048
#define ND  1024
#define NH  16
#define NDK 64
#define NTOK (NB*NS)          // 4096

// Scratch (static __device__ arrays; no allocation allowed)
__device__ __nv_bfloat16 g_qh[NB*NS*ND];  // Q hi/lo (bf16), [b,h,s,dk]
__device__ __nv_bfloat16 g_ql[NB*NS*ND];
__device__ __nv_bfloat16 g_kh[NB*NS*ND];  // K hi/lo (bf16)
__device__ __nv_bfloat16 g_kl[NB*NS*ND];
__device__ float g_v[NB*NS*ND];           // V (tf32-rounded fp32)
__device__ __nv_bfloat16 g_xh[NTOK*ND];   // activation hi (x, then att), blocked
__device__ __nv_bfloat16 g_xl[NTOK*ND];   // activation lo, blocked
__device__ __nv_bfloat16 g_wh[4*ND*ND];   // weights hi, blocked (Wq,Wk,Wv,Wo)
__device__ __nv_bfloat16 g_wl[4*ND*ND];   // weights lo, blocked

// ---------------------------------------------------------------------------
// helpers
// ---------------------------------------------------------------------------
__device__ __forceinline__ float tf32r(float v) {
    uint32_t u;
    asm("cvt.rna.tf32.f32 %0, %1;" : "=r"(u) : "f"(v));
    return __uint_as_float(u);
}

__device__ __forceinline__ void splitbf(float v, __nv_bfloat16& h, __nv_bfloat16& l) {
    h = __float2bfloat16(v);
    l = __float2bfloat16(v - __bfloat162float(h));
}

// tf32 m16n8k8 (attention PV)
__device__ __forceinline__ void mma8(float* c, const uint32_t* a, const uint32_t* b) {
    asm volatile(
        "mma.sync.aligned.m16n8k8.row.col.f32.tf32.tf32.f32 "
        "{%0,%1,%2,%3}, {%4,%5,%6,%7}, {%8,%9}, {%0,%1,%2,%3};"
        : "+f"(c[0]), "+f"(c[1]), "+f"(c[2]), "+f"(c[3])
        : "r"(a[0]), "r"(a[1]), "r"(a[2]), "r"(a[3]),
          "r"(b[0]), "r"(b[1]));
}

// bf16 m16n8k16 (projections + QK)
__device__ __forceinline__ void mma16(float* c, const uint32_t* a, const uint32_t* b) {
    asm volatile(
        "mma.sync.aligned.m16n8k16.row.col.f32.bf16.bf16.f32 "
        "{%0,%1,%2,%3}, {%4,%5,%6,%7}, {%8,%9}, {%0,%1,%2,%3};"
        : "+f"(c[0]), "+f"(c[1]), "+f"(c[2]), "+f"(c[3])
        : "r"(a[0]), "r"(a[1]), "r"(a[2]), "r"(a[3]),
          "r"(b[0]), "r"(b[1]));
}

// ldmatrix x4: four 8x8 b16 tiles
__device__ __forceinline__ void ldsm4(uint32_t* r, uint32_t addr) {
    asm volatile("ldmatrix.sync.aligned.m8n8.x4.shared.b16 {%0,%1,%2,%3}, [%4];"
        : "=r"(r[0]), "=r"(r[1]), "=r"(r[2]), "=r"(r[3]) : "r"(addr));
}

__device__ __forceinline__ void cpa16(uint32_t dst, const void* src) {
    asm volatile("cp.async.cg.shared.global [%0], [%1], 16;" :: "r"(dst), "l"(src));
}

__device__ __forceinline__ uint32_t smem_u32(const void* p) {
    uint32_t a;
    asm("{ .reg .u64 t; cvta.to.shared.u64 t, %1; cvt.u32.u64 %0, t; }" : "=r"(a) : "l"(p));
    return a;
}

// ---------------------------------------------------------------------------
// Prep kernels: blocked bf16 hi/lo layouts (32-element k-chunks, 64B rows).
// ---------------------------------------------------------------------------
__global__ void prep_x(const float* __restrict__ src,
                       __nv_bfloat16* __restrict__ dh, __nv_bfloat16* __restrict__ dl) {
    int idx = (blockIdx.x * blockDim.x + threadIdx.x) * 4;
    int m  = idx >> 10;
    int kk = idx & 1023;
    float4 v = *reinterpret_cast<const float4*>(&src[idx]);
    size_t o = ((size_t)(kk >> 5) * NTOK + m) * 32 + (kk & 31);
    __nv_bfloat16 h0, l0, h1, l1, h2, l2, h3, l3;
    splitbf(v.x, h0, l0); splitbf(v.y, h1, l1);
    splitbf(v.z, h2, l2); splitbf(v.w, h3, l3);
    *reinterpret_cast<__nv_bfloat162*>(&dh[o])     = __nv_bfloat162(h0, h1);
    *reinterpret_cast<__nv_bfloat162*>(&dh[o + 2]) = __nv_bfloat162(h2, h3);
    *reinterpret_cast<__nv_bfloat162*>(&dl[o])     = __nv_bfloat162(l0, l1);
    *reinterpret_cast<__nv_bfloat162*>(&dl[o + 2]) = __nv_bfloat162(l2, l3);
}

__global__ void prep_w(const float* __restrict__ w0, const float* __restrict__ w1,
                       const float* __restrict__ w2, const float* __restrict__ w3,
                       __nv_bfloat16* __restrict__ dh, __nv_bfloat16* __restrict__ dl) {
    int z = blockIdx.y;
    const float* s = (z == 0) ? w0 : (z == 1) ? w1 : (z == 2) ? w2 : w3;
    int idx = (blockIdx.x * blockDim.x + threadIdx.x) * 4;
    int n  = idx >> 10;
    int kk = idx & 1023;
    float4 v = *reinterpret_cast<const float4*>(&s[idx]);
    size_t o = ((size_t)(z*32 + (kk >> 5)) * ND + n) * 32 + (kk & 31);
    __nv_bfloat16 h0, l0, h1, l1, h2, l2, h3, l3;
    splitbf(v.x, h0, l0); splitbf(v.y, h1, l1);
    splitbf(v.z, h2, l2); splitbf(v.w, h3, l3);
    *reinterpret_cast<__nv_bfloat162*>(&dh[o])     = __nv_bfloat162(h0, h1);
    *reinterpret_cast<__nv_bfloat162*>(&dh[o + 2]) = __nv_bfloat162(h2, h3);
    *reinterpret_cast<__nv_bfloat162*>(&dl[o])     = __nv_bfloat162(l0, l1);
    *reinterpret_cast<__nv_bfloat162*>(&dl[o + 2]) = __nv_bfloat162(l2, l3);
}

// ---------------------------------------------------------------------------
// bf16x3 GEMM with ldmatrix fragment loads: CTA 128x128, 8 warps (4m x 2n),
// warp 32x64, K-chunk 32 (2 x k16 steps).
// ---------------------------------------------------------------------------
#define TRW  20
#define TSZW (128*TRW)
#define TSZB (TSZW*4)
#define GEMM_SMEM (2*4*TSZB)            // 81920

template<int MODE>
__global__ __launch_bounds__(256, 2) void gemm_bf(const __nv_bfloat16* __restrict__ Ah,
                                                  const __nv_bfloat16* __restrict__ Al,
                                                  const __nv_bfloat16* __restrict__ Bh,
                                                  const __nv_bfloat16* __restrict__ Bl,
                                                  __nv_bfloat16* __restrict__ qh,
                                                  __nv_bfloat16* __restrict__ ql,
                                                  __nv_bfloat16* __restrict__ kh,
                                                  __nv_bfloat16* __restrict__ kl,
                                                  float* __restrict__ v,
                                                  float* __restrict__ outp) {
    extern __shared__ uint32_t sw[];
    const uint32_t sbase = smem_u32(sw);

    const int tid  = threadIdx.x;
    const int lane = tid & 31;
    const int warp = tid >> 5;
    const int wm = (warp & 3) * 32;
    const int wn = (warp >> 2) * 64;
    const int z  = (MODE == 1) ? (int)blockIdx.z : 3;
    const int m0 = blockIdx.y * 128;
    const int n0 = blockIdx.x * 128;
    const int g = lane >> 2;
    const int t = lane & 3;

    // ldmatrix per-thread byte offsets within a tile
    const int arow = (lane & 7) + ((lane >> 3) & 1) * 8;   // A: t8-15 -> m+8
    const int akb  = ((lane >> 4) & 1) * 16;               // A: t16+ -> k-hi (4 words)
    const int aoff = (wm + arow) * 80 + akb;
    const int brow = (lane & 7) + ((lane >> 4) & 1) * 8;   // B: t16+ -> next n-tile
    const int bkb  = ((lane >> 3) & 1) * 16;               // B: t8-15 -> k-hi
    const int boff = (wn + brow) * 80 + bkb;

    auto stage = [&](int buf, int ch) {
        #pragma unroll
        for (int tI = 0; tI < 4; tI++) {
            const __nv_bfloat16* src = (tI == 0) ? Ah : (tI == 1) ? Al
                                      : (tI == 2) ? Bh : Bl;
            #pragma unroll
            for (int it = 0; it < 2; it++) {
                const int i = tid + it*256;
                const int row = i >> 2, part = i & 3;
                const size_t grow = (tI < 2)
                    ? ((size_t)ch * NTOK + m0 + row)
                    : ((size_t)(z*32 + ch) * ND + n0 + row);
                cpa16(sbase + (buf*4 + tI)*TSZB + row*80 + part*16,
                      (const char*)src + grow*64 + part*16);
            }
        }
        asm volatile("cp.async.commit_group;");
    };

    float c[2][8][4] = {};
    stage(0, 0);

    for (int i = 0; i < 32; i++) {
        const int buf = i & 1;
        asm volatile("cp.async.wait_group 0;");
        __syncthreads();
        if (i + 1 < 32) stage(1 - buf, i + 1);

        const uint32_t bAH = sbase + (buf*4 + 0)*TSZB;
        const uint32_t bAL = sbase + (buf*4 + 1)*TSZB;
        const uint32_t bBH = sbase + (buf*4 + 2)*TSZB;
        const uint32_t bBL = sbase + (buf*4 + 3)*TSZB;

        #pragma unroll
        for (int ks = 0; ks < 2; ks++) {
            const int kbB = ks * 32;           // 8 words
            uint32_t ah[2][4], al[2][4];
            ldsm4(ah[0], bAH + aoff + kbB);
            ldsm4(ah[1], bAH + aoff + 16*80 + kbB);
            ldsm4(al[0], bAL + aoff + kbB);
            ldsm4(al[1], bAL + aoff + 16*80 + kbB);
            #pragma unroll
            for (int ntp = 0; ntp < 4; ntp++) {
                uint32_t bh4[4], bl4[4];
                ldsm4(bh4, bBH + boff + ntp*16*80 + kbB);
                ldsm4(bl4, bBL + boff + ntp*16*80 + kbB);
                const int nt0 = 2*ntp, nt1 = 2*ntp + 1;
                mma16(c[0][nt0], al[0], bh4);
                mma16(c[0][nt0], ah[0], bl4);
                mma16(c[0][nt0], ah[0], bh4);
                mma16(c[1][nt0], al[1], bh4);
                mma16(c[1][nt0], ah[1], bl4);
                mma16(c[1][nt0], ah[1], bh4);
                mma16(c[0][nt1], al[0], bh4 + 2);
                mma16(c[0][nt1], ah[0], bl4 + 2);
                mma16(c[0][nt1], ah[0], bh4 + 2);
                mma16(c[1][nt1], al[1], bh4 + 2);
                mma16(c[1][nt1], ah[1], bl4 + 2);
                mma16(c[1][nt1], ah[1], bh4 + 2);
            }
        }
    }

    #pragma unroll
    for (int mt = 0; mt < 2; mt++) {
        #pragma unroll
        for (int nt = 0; nt < 8; nt++) {
            const int row = m0 + wm + mt*16 + g;
            const int col = n0 + wn + nt*8 + 2*t;
            #pragma unroll
            for (int half = 0; half < 2; half++) {
                const int r = row + half*8;
                float v0 = c[mt][nt][half*2 + 0];
                float v1 = c[mt][nt][half*2 + 1];
                if (MODE == 0) {
                    outp[(size_t)r*ND + col    ] = v0;
                    outp[(size_t)r*ND + col + 1] = v1;
                } else {
                    const int b = r >> 11;
                    const int s = r & (NS - 1);
                    const int h  = col >> 6;
                    const int dk = col & 63;       // even
                    const size_t oidx = (size_t)((b*NH + h)*NS + s)*NDK + dk;
                    if (z == 2) {
                        float* dst = &v[oidx];
                        dst[0] = tf32r(v0);
                        dst[1] = tf32r(v1);
                    } else {
                        float inv = powf(10000.0f, -(float)dk / 64.0f);
                        float ang = (float)s * inv;
                        float sn, cs;
                        sincosf(ang, &sn, &cs);
                        float r0 = v0*cs - v1*sn;
                        float r1 = v0*sn + v1*cs;
                        __nv_bfloat16 h0, l0, h1, l1;
                        splitbf(r0, h0, l0);
                        splitbf(r1, h1, l1);
                        __nv_bfloat16* dh = (z == 0) ? qh : kh;
                        __nv_bfloat16* dl = (z == 0) ? ql : kl;
                        *reinterpret_cast<__nv_bfloat162*>(&dh[oidx]) = __nv_bfloat162(h0, h1);
                        *reinterpret_cast<__nv_bfloat162*>(&dl[oidx]) = __nv_bfloat162(l0, l1);
                    }
                }
            }
        }
    }
}

// ---------------------------------------------------------------------------
// Tensor-core causal flash attention v5: AK=64, 2 CTAs/SM, ldmatrix QK loads.
// 8 warps, each = 16 q-rows x all 64 keys; P in registers (shuffle assembly);
// double-buffered cp.async K/V; ONE barrier per chunk.
// QK^T: bf16x3 mma16. P*V: 1xTF32.
// ---------------------------------------------------------------------------
#define AQ 128
#define AK 64
#define QKW 36                 // Q/K row stride in 32-bit words (144 B)
#define VSTR 72                // V row stride in floats
#define QW_F  (AQ*QKW)
#define KW_F  (AK*QKW)
#define VW_F  (AK*VSTR)
#define ATTN_SMEM (27648*4)

__global__ __launch_bounds__(256, 2) void attn_tc(const __nv_bfloat16* __restrict__ qh,
                                                  const __nv_bfloat16* __restrict__ ql,
                                                  const __nv_bfloat16* __restrict__ kh,
                                                  const __nv_bfloat16* __restrict__ kl,
                                                  const float* __restrict__ v,
                                                  __nv_bfloat16* __restrict__ oh,
                                                  __nv_bfloat16* __restrict__ ol) {
    extern __shared__ uint32_t smw[];
    uint32_t* QhS = smw;                    // [AQ][QKW]
    uint32_t* QlS = QhS + QW_F;
    uint32_t* KW  = QlS + QW_F;             // [2][Kh|Kl][AK][QKW]
    float*    VS  = (float*)(KW + 2*2*KW_F);// [2][AK][VSTR]

    const int bh = blockIdx.y;
    const int qi = (int)gridDim.x - 1 - (int)blockIdx.x;
    const int q0 = qi * AQ;
    const int tid = threadIdx.x;
    const int lane = tid & 31;
    const int warp = tid >> 5;
    const int g = lane >> 2, t = lane & 3;
    const int wm = warp * 16;

    const __nv_bfloat16* qhb = qh + (size_t)bh * NS * NDK;
    const __nv_bfloat16* qlb = ql + (size_t)bh * NS * NDK;
    const __nv_bfloat16* khb = kh + (size_t)bh * NS * NDK;
    const __nv_bfloat16* klb = kl + (size_t)bh * NS * NDK;
    const float*         vbp = v  + (size_t)bh * NS * NDK;

    // stage Q hi/lo tiles (128 rows x 128 B each)
    for (int i = tid; i < AQ*8; i += 256) {
        int r = i >> 3, c = i & 7;
        uint4 xh4 = *reinterpret_cast<const uint4*>(
            (const char*)qhb + (size_t)(q0+r)*128 + c*16);
        uint4 xl4 = *reinterpret_cast<const uint4*>(
            (const char*)qlb + (size_t)(q0+r)*128 + c*16);
        *reinterpret_cast<uint4*>(&QhS[r*QKW + c*4]) = xh4;
        *reinterpret_cast<uint4*>(&QlS[r*QKW + c*4]) = xl4;
    }

    auto issueKV = [&](int buf, int k0) {
        uint32_t* KhD = KW + buf*2*KW_F;
        uint32_t* KlD = KhD + KW_F;
        float*    VD  = VS + buf*VW_F;
        #pragma unroll
        for (int it = 0; it < 2; it++) {
            int i = tid + it*256;
            int r = i >> 3, c = i & 7;
            cpa16(smem_u32(&KhD[r*QKW + c*4]),
                  (const char*)khb + (size_t)(k0+r)*128 + c*16);
            cpa16(smem_u32(&KlD[r*QKW + c*4]),
                  (const char*)klb + (size_t)(k0+r)*128 + c*16);
        }
        #pragma unroll
        for (int it = 0; it < 4; it++) {
            int i = tid + it*256;
            int r = i >> 4, c = (i & 15) << 2;
            cpa16(smem_u32(&VD[r*VSTR + c]), &vbp[(size_t)(k0+r)*NDK + c]);
        }
        asm volatile("cp.async.commit_group;");
    };

    // ldmatrix per-thread offsets (bytes; row stride 144)
    const int qrow = wm + (lane & 7) + ((lane >> 3) & 1) * 8;
    const int qkbo = ((lane >> 4) & 1) * 16;
    const uint32_t qhAddr = smem_u32(QhS) + qrow*144 + qkbo;
    const uint32_t qlAddr = smem_u32(QlS) + qrow*144 + qkbo;
    const int krow = (lane & 7) + ((lane >> 4) & 1) * 8;
    const int kkbo = ((lane >> 3) & 1) * 16;
    const uint32_t kwBase = smem_u32(KW) + krow*144 + kkbo;

    float oacc[8][4] = {};
    float sacc[8][4];
    float Lacc[2] = {0.f, 0.f};

    const int nch = q0/AK + 2;
    issueKV(0, 0);

    for (int ch = 0; ch < nch; ch++) {
        const int buf = ch & 1;
        const int k0 = ch * AK;
        asm volatile("cp.async.wait_group 0;");
        __syncthreads();
        if (ch + 1 < nch) issueKV(1 - buf, (ch + 1) * AK);

        const uint32_t khAddr = kwBase + buf*2*KW_F*4;
        const uint32_t klAddr = khAddr + KW_F*4;
        const float*   Vsb = VS + buf*VW_F;

        // S = Q K^T, bf16x3 via ldmatrix (pure LDSM + HMMA)
        #pragma unroll
        for (int i = 0; i < 8; i++)
            #pragma unroll
            for (int j = 0; j < 4; j++) sacc[i][j] = 0.f;
        #pragma unroll
        for (int ks = 0; ks < 4; ks++) {
            const int kbB = ks * 32;
            uint32_t qhf[4], qlf[4];
            ldsm4(qhf, qhAddr + kbB);
            ldsm4(qlf, qlAddr + kbB);
            #pragma unroll
            for (int ntp = 0; ntp < 4; ntp++) {
                uint32_t kh4[4], kl4[4];
                ldsm4(kh4, khAddr + ntp*16*144 + kbB);
                ldsm4(kl4, klAddr + ntp*16*144 + kbB);
                const int nt0 = 2*ntp, nt1 = 2*ntp + 1;
                mma16(sacc[nt0], qlf, kh4);
                mma16(sacc[nt0], qhf, kl4);
                mma16(sacc[nt0], qhf, kh4);
                mma16(sacc[nt1], qlf, kh4 + 2);
                mma16(sacc[nt1], qhf, kl4 + 2);
                mma16(sacc[nt1], qhf, kh4 + 2);
            }
        }

        // softmax weights (constant shift), mask, tf32 round -> sacc = P
        const bool need_mask = (k0 + AK - 1 > q0);
        #pragma unroll
        for (int nt = 0; nt < 8; nt++) {
            #pragma unroll
            for (int e2 = 0; e2 < 4; e2++) {
                const int col = nt*8 + 2*t + (e2 & 1);
                const int rq  = q0 + wm + g + 8*(e2 >> 1);
                float p = __expf(fminf(fmaxf(sacc[nt][e2], -80.f), 80.f)*0.125f - 10.f);
                if (need_mask && (k0 + col > rq)) p = 0.f;
                p = tf32r(p);
                sacc[nt][e2] = p;
                Lacc[e2 >> 1] += p;
            }
        }

        // O += P * V (1xTF32): P frags via in-warp shuffles
        #pragma unroll
        for (int ks = 0; ks < 8; ks++) {
            const int kp = ks*8;
            const int srcA = (g << 2) + (t >> 1);
            const int srcB = srcA + 2;
            float v00 = __shfl_sync(0xffffffffu, sacc[ks][0], srcA);
            float v01 = __shfl_sync(0xffffffffu, sacc[ks][1], srcA);
            float v10 = __shfl_sync(0xffffffffu, sacc[ks][2], srcA);
            float v11 = __shfl_sync(0xffffffffu, sacc[ks][3], srcA);
            float w00 = __shfl_sync(0xffffffffu, sacc[ks][0], srcB);
            float w01 = __shfl_sync(0xffffffffu, sacc[ks][1], srcB);
            float w10 = __shfl_sync(0xffffffffu, sacc[ks][2], srcB);
            float w11 = __shfl_sync(0xffffffffu, sacc[ks][3], srcB);
            const bool odd = (t & 1);
            uint32_t pa[4];
            pa[0] = __float_as_uint(odd ? v01 : v00);
            pa[1] = __float_as_uint(odd ? v11 : v10);
            pa[2] = __float_as_uint(odd ? w01 : w00);
            pa[3] = __float_as_uint(odd ? w11 : w10);
            #pragma unroll
            for (int nt = 0; nt < 8; nt++) {
                uint32_t vb2[2];
                vb2[0] = __float_as_uint(Vsb[(kp + t    )*VSTR + nt*8 + g]);
                vb2[1] = __float_as_uint(Vsb[(kp + t + 4)*VSTR + nt*8 + g]);
                mma8(oacc[nt], pa, vb2);
            }
        }
    }

    float l0 = Lacc[0];
    l0 += __shfl_xor_sync(0xffffffffu, l0, 1);
    l0 += __shfl_xor_sync(0xffffffffu, l0, 2);
    float l1 = Lacc[1];
    l1 += __shfl_xor_sync(0xffffffffu, l1, 1);
    l1 += __shfl_xor_sync(0xffffffffu, l1, 2);
    const float inv0 = 1.0f / l0;
    const float inv1 = 1.0f / l1;

    // write att split to blocked bf16 layout: kk = h*64 + cc
    const int b = bh >> 4, h = bh & 15;
    const int tok0 = b*NS + q0 + wm + g;
    const int tok1 = tok0 + 8;
    #pragma unroll
    for (int nt = 0; nt < 8; nt++) {
        const int cc = nt*8 + 2*t;
        const int kk = h*64 + cc;
        const size_t o0 = ((size_t)(kk >> 5)*NTOK + tok0)*32 + (kk & 31);
        const size_t o1 = ((size_t)(kk >> 5)*NTOK + tok1)*32 + (kk & 31);
        __nv_bfloat16 h0, lo0, h1, lo1;
        splitbf(oacc[nt][0]*inv0, h0, lo0);
        splitbf(oacc[nt][1]*inv0, h1, lo1);
        *reinterpret_cast<__nv_bfloat162*>(&oh[o0]) = __nv_bfloat162(h0, h1);
        *reinterpret_cast<__nv_bfloat162*>(&ol[o0]) = __nv_bfloat162(lo0, lo1);
        splitbf(oacc[nt][2]*inv1, h0, lo0);
        splitbf(oacc[nt][3]*inv1, h1, lo1);
        *reinterpret_cast<__nv_bfloat162*>(&oh[o1]) = __nv_bfloat162(h0, h1);
        *reinterpret_cast<__nv_bfloat162*>(&ol[o1]) = __nv_bfloat162(lo0, lo1);
    }
}

// ---------------------------------------------------------------------------
// Launch (graph-capturable: kernel launches only)
// ---------------------------------------------------------------------------
extern "C" void kernel_launch(void* const* d_in, const int* in_sizes, int n_in,
                              void* d_out, int out_size) {
    const float* x  = (const float*)d_in[0];
    const float* Wq = (const float*)d_in[1];
    const float* Wk = (const float*)d_in[2];
    const float* Wv = (const float*)d_in[3];
    const float* Wo = (const float*)d_in[4];
    float* out = (float*)d_out;

    float *vp;
    __nv_bfloat16 *qhp, *qlp, *khp, *klp, *xh, *xl, *wh, *wl;
    cudaGetSymbolAddress((void**)&qhp, g_qh);
    cudaGetSymbolAddress((void**)&qlp, g_ql);
    cudaGetSymbolAddress((void**)&khp, g_kh);
    cudaGetSymbolAddress((void**)&klp, g_kl);
    cudaGetSymbolAddress((void**)&vp,  g_v);
    cudaGetSymbolAddress((void**)&xh,  g_xh);
    cudaGetSymbolAddress((void**)&xl,  g_xl);
    cudaGetSymbolAddress((void**)&wh,  g_wh);
    cudaGetSymbolAddress((void**)&wl,  g_wl);

    cudaFuncSetAttribute(attn_tc,    cudaFuncAttributeMaxDynamicSharedMemorySize, ATTN_SMEM);
    cudaFuncSetAttribute(gemm_bf<0>, cudaFuncAttributeMaxDynamicSharedMemorySize, GEMM_SMEM);
    cudaFuncSetAttribute(gemm_bf<1>, cudaFuncAttributeMaxDynamicSharedMemorySize, GEMM_SMEM);

    prep_x<<<NTOK*ND/4/256, 256>>>(x, xh, xl);
    prep_w<<<dim3(ND*ND/4/256, 4), 256>>>(Wq, Wk, Wv, Wo, wh, wl);

    gemm_bf<1><<<dim3(ND/128, NTOK/128, 3), 256, GEMM_SMEM>>>(
        xh, xl, wh, wl, qhp, qlp, khp, klp, vp, nullptr);

    attn_tc<<<dim3(NS/AQ, NB*NH), 256, ATTN_SMEM>>>(qhp, qlp, khp, klp, vp, xh, xl);

    gemm_bf<0><<<dim3(ND/128, NTOK/128, 1), 256, GEMM_SMEM>>>(
        xh, xl, wh, wl, nullptr, nullptr, nullptr, nullptr, nullptr, out);
}

// round 16
// speedup vs baseline: 1.2529x; 1.2529x over previous
#include <cuda_runtime.h>
#include <cuda_bf16.h>
#include <math.h>
#include <stdint.h>

// Problem constants
#define NB  2
#define NS  2048
#define ND  1024
#define NH  16
#define NDK 64
#define NTOK (NB*NS)          // 4096

// Scratch (static __device__ arrays; no allocation allowed)
__device__ __nv_bfloat16 g_qh[NB*NS*ND];  // Q hi/lo (bf16), [b,h,s,dk]
__device__ __nv_bfloat16 g_ql[NB*NS*ND];
__device__ __nv_bfloat16 g_kh[NB*NS*ND];  // K hi/lo (bf16)
__device__ __nv_bfloat16 g_kl[NB*NS*ND];
__device__ float g_v[NB*NS*ND];           // V (tf32-rounded fp32)
__device__ __nv_bfloat16 g_xh[NTOK*ND];   // activation hi (x, then att), blocked
__device__ __nv_bfloat16 g_xl[NTOK*ND];   // activation lo, blocked
__device__ __nv_bfloat16 g_wh[4*ND*ND];   // weights hi, blocked (Wq,Wk,Wv,Wo)
__device__ __nv_bfloat16 g_wl[4*ND*ND];   // weights lo, blocked
__device__ float2 g_rope[NS*32];          // (cos, sin) per (s, pair)

// ---------------------------------------------------------------------------
// helpers
// ---------------------------------------------------------------------------
__device__ __forceinline__ float tf32r(float v) {
    uint32_t u;
    asm("cvt.rna.tf32.f32 %0, %1;" : "=r"(u) : "f"(v));
    return __uint_as_float(u);
}

__device__ __forceinline__ void splitbf(float v, __nv_bfloat16& h, __nv_bfloat16& l) {
    h = __float2bfloat16(v);
    l = __float2bfloat16(v - __bfloat162float(h));
}

// tf32 m16n8k8 (attention PV)
__device__ __forceinline__ void mma8(float* c, const uint32_t* a, const uint32_t* b) {
    asm volatile(
        "mma.sync.aligned.m16n8k8.row.col.f32.tf32.tf32.f32 "
        "{%0,%1,%2,%3}, {%4,%5,%6,%7}, {%8,%9}, {%0,%1,%2,%3};"
        : "+f"(c[0]), "+f"(c[1]), "+f"(c[2]), "+f"(c[3])
        : "r"(a[0]), "r"(a[1]), "r"(a[2]), "r"(a[3]),
          "r"(b[0]), "r"(b[1]));
}

// bf16 m16n8k16 (projections + QK)
__device__ __forceinline__ void mma16(float* c, const uint32_t* a, const uint32_t* b) {
    asm volatile(
        "mma.sync.aligned.m16n8k16.row.col.f32.bf16.bf16.f32 "
        "{%0,%1,%2,%3}, {%4,%5,%6,%7}, {%8,%9}, {%0,%1,%2,%3};"
        : "+f"(c[0]), "+f"(c[1]), "+f"(c[2]), "+f"(c[3])
        : "r"(a[0]), "r"(a[1]), "r"(a[2]), "r"(a[3]),
          "r"(b[0]), "r"(b[1]));
}

__device__ __forceinline__ void cpa16(uint32_t dst, const void* src) {
    asm volatile("cp.async.cg.shared.global [%0], [%1], 16;" :: "r"(dst), "l"(src));
}

__device__ __forceinline__ uint32_t smem_u32(const void* p) {
    uint32_t a;
    asm("{ .reg .u64 t; cvta.to.shared.u64 t, %1; cvt.u32.u64 %0, t; }" : "=r"(a) : "l"(p));
    return a;
}

// ---------------------------------------------------------------------------
// Prep kernels
// ---------------------------------------------------------------------------
__global__ void prep_rope() {
    int idx = blockIdx.x * blockDim.x + threadIdx.x;   // NS*32
    int s = idx >> 5, pair = idx & 31;
    float inv = powf(10000.0f, -(float)(2*pair) / 64.0f);   // same formula as before
    float ang = (float)s * inv;
    float sn, cs;
    sincosf(ang, &sn, &cs);
    g_rope[idx] = make_float2(cs, sn);
}

__global__ void prep_x(const float* __restrict__ src,
                       __nv_bfloat16* __restrict__ dh, __nv_bfloat16* __restrict__ dl) {
    int idx = (blockIdx.x * blockDim.x + threadIdx.x) * 4;
    int m  = idx >> 10;
    int kk = idx & 1023;
    float4 v = *reinterpret_cast<const float4*>(&src[idx]);
    size_t o = ((size_t)(kk >> 5) * NTOK + m) * 32 + (kk & 31);
    __nv_bfloat16 h0, l0, h1, l1, h2, l2, h3, l3;
    splitbf(v.x, h0, l0); splitbf(v.y, h1, l1);
    splitbf(v.z, h2, l2); splitbf(v.w, h3, l3);
    *reinterpret_cast<__nv_bfloat162*>(&dh[o])     = __nv_bfloat162(h0, h1);
    *reinterpret_cast<__nv_bfloat162*>(&dh[o + 2]) = __nv_bfloat162(h2, h3);
    *reinterpret_cast<__nv_bfloat162*>(&dl[o])     = __nv_bfloat162(l0, l1);
    *reinterpret_cast<__nv_bfloat162*>(&dl[o + 2]) = __nv_bfloat162(l2, l3);
}

__global__ void prep_w(const float* __restrict__ w0, const float* __restrict__ w1,
                       const float* __restrict__ w2, const float* __restrict__ w3,
                       __nv_bfloat16* __restrict__ dh, __nv_bfloat16* __restrict__ dl) {
    int z = blockIdx.y;
    const float* s = (z == 0) ? w0 : (z == 1) ? w1 : (z == 2) ? w2 : w3;
    int idx = (blockIdx.x * blockDim.x + threadIdx.x) * 4;
    int n  = idx >> 10;
    int kk = idx & 1023;
    float4 v = *reinterpret_cast<const float4*>(&s[idx]);
    size_t o = ((size_t)(z*32 + (kk >> 5)) * ND + n) * 32 + (kk & 31);
    __nv_bfloat16 h0, l0, h1, l1, h2, l2, h3, l3;
    splitbf(v.x, h0, l0); splitbf(v.y, h1, l1);
    splitbf(v.z, h2, l2); splitbf(v.w, h3, l3);
    *reinterpret_cast<__nv_bfloat162*>(&dh[o])     = __nv_bfloat162(h0, h1);
    *reinterpret_cast<__nv_bfloat162*>(&dh[o + 2]) = __nv_bfloat162(h2, h3);
    *reinterpret_cast<__nv_bfloat162*>(&dl[o])     = __nv_bfloat162(l0, l1);
    *reinterpret_cast<__nv_bfloat162*>(&dl[o + 2]) = __nv_bfloat162(l2, l3);
}

// ---------------------------------------------------------------------------
// bf16x3 GEMM (R14 body, scalar LDS): CTA 128x128, 8 warps (4m x 2n),
// warp 32x64, K-chunk 32 (2 x k16 steps). Epilogue RoPE via lookup table.
// ---------------------------------------------------------------------------
#define TRW  20
#define TSZW (128*TRW)
#define TSZB (TSZW*4)
#define GEMM_SMEM (2*4*TSZB)            // 81920

template<int MODE>
__global__ __launch_bounds__(256, 2) void gemm_bf(const __nv_bfloat16* __restrict__ Ah,
                                                  const __nv_bfloat16* __restrict__ Al,
                                                  const __nv_bfloat16* __restrict__ Bh,
                                                  const __nv_bfloat16* __restrict__ Bl,
                                                  __nv_bfloat16* __restrict__ qh,
                                                  __nv_bfloat16* __restrict__ ql,
                                                  __nv_bfloat16* __restrict__ kh,
                                                  __nv_bfloat16* __restrict__ kl,
                                                  float* __restrict__ v,
                                                  float* __restrict__ outp) {
    extern __shared__ uint32_t sw[];
    const uint32_t sbase = smem_u32(sw);

    const int tid  = threadIdx.x;
    const int lane = tid & 31;
    const int warp = tid >> 5;
    const int wm = (warp & 3) * 32;
    const int wn = (warp >> 2) * 64;
    const int z  = (MODE == 1) ? (int)blockIdx.z : 3;
    const int m0 = blockIdx.y * 128;
    const int n0 = blockIdx.x * 128;
    const int g = lane >> 2;
    const int t = lane & 3;

    auto stage = [&](int buf, int ch) {
        #pragma unroll
        for (int tI = 0; tI < 4; tI++) {
            const __nv_bfloat16* src = (tI == 0) ? Ah : (tI == 1) ? Al
                                      : (tI == 2) ? Bh : Bl;
            #pragma unroll
            for (int it = 0; it < 2; it++) {
                const int i = tid + it*256;
                const int row = i >> 2, part = i & 3;
                const size_t grow = (tI < 2)
                    ? ((size_t)ch * NTOK + m0 + row)
                    : ((size_t)(z*32 + ch) * ND + n0 + row);
                cpa16(sbase + (buf*4 + tI)*TSZB + row*80 + part*16,
                      (const char*)src + grow*64 + part*16);
            }
        }
        asm volatile("cp.async.commit_group;");
    };

    float c[2][8][4] = {};
    stage(0, 0);

    for (int i = 0; i < 32; i++) {
        const int buf = i & 1;
        asm volatile("cp.async.wait_group 0;");
        __syncthreads();
        if (i + 1 < 32) stage(1 - buf, i + 1);

        const uint32_t* AsH = sw + (buf*4 + 0)*TSZW;
        const uint32_t* AsL = sw + (buf*4 + 1)*TSZW;
        const uint32_t* BsH = sw + (buf*4 + 2)*TSZW;
        const uint32_t* BsL = sw + (buf*4 + 3)*TSZW;

        #pragma unroll
        for (int ks = 0; ks < 2; ks++) {
            const int kb = ks * 8;
            uint32_t ah[2][4], al[2][4];
            #pragma unroll
            for (int mt = 0; mt < 2; mt++) {
                const int r0 = (wm + mt*16 + g)*TRW;
                ah[mt][0] = AsH[r0         + kb + t];
                ah[mt][1] = AsH[r0 + 8*TRW + kb + t];
                ah[mt][2] = AsH[r0         + kb + t + 4];
                ah[mt][3] = AsH[r0 + 8*TRW + kb + t + 4];
                al[mt][0] = AsL[r0         + kb + t];
                al[mt][1] = AsL[r0 + 8*TRW + kb + t];
                al[mt][2] = AsL[r0         + kb + t + 4];
                al[mt][3] = AsL[r0 + 8*TRW + kb + t + 4];
            }
            #pragma unroll
            for (int nt = 0; nt < 8; nt++) {
                const int rb = (wn + nt*8 + g)*TRW;
                uint32_t bh2[2], bl2[2];
                bh2[0] = BsH[rb + kb + t];
                bh2[1] = BsH[rb + kb + t + 4];
                bl2[0] = BsL[rb + kb + t];
                bl2[1] = BsL[rb + kb + t + 4];
                mma16(c[0][nt], al[0], bh2);
                mma16(c[0][nt], ah[0], bl2);
                mma16(c[0][nt], ah[0], bh2);
                mma16(c[1][nt], al[1], bh2);
                mma16(c[1][nt], ah[1], bl2);
                mma16(c[1][nt], ah[1], bh2);
            }
        }
    }

    #pragma unroll
    for (int mt = 0; mt < 2; mt++) {
        #pragma unroll
        for (int nt = 0; nt < 8; nt++) {
            const int row = m0 + wm + mt*16 + g;
            const int col = n0 + wn + nt*8 + 2*t;
            #pragma unroll
            for (int half = 0; half < 2; half++) {
                const int r = row + half*8;
                float v0 = c[mt][nt][half*2 + 0];
                float v1 = c[mt][nt][half*2 + 1];
                if (MODE == 0) {
                    outp[(size_t)r*ND + col    ] = v0;
                    outp[(size_t)r*ND + col + 1] = v1;
                } else {
                    const int b = r >> 11;
                    const int s = r & (NS - 1);
                    const int h  = col >> 6;
                    const int dk = col & 63;       // even
                    const size_t oidx = (size_t)((b*NH + h)*NS + s)*NDK + dk;
                    if (z == 2) {
                        float* dst = &v[oidx];
                        dst[0] = tf32r(v0);
                        dst[1] = tf32r(v1);
                    } else {
                        // RoPE via table (bit-identical to inline powf/sincosf)
                        float2 cssn = g_rope[s*32 + (dk >> 1)];
                        float r0 = v0*cssn.x - v1*cssn.y;
                        float r1 = v0*cssn.y + v1*cssn.x;
                        __nv_bfloat16 h0, l0, h1, l1;
                        splitbf(r0, h0, l0);
                        splitbf(r1, h1, l1);
                        __nv_bfloat16* dh = (z == 0) ? qh : kh;
                        __nv_bfloat16* dl = (z == 0) ? ql : kl;
                        *reinterpret_cast<__nv_bfloat162*>(&dh[oidx]) = __nv_bfloat162(h0, h1);
                        *reinterpret_cast<__nv_bfloat162*>(&dl[oidx]) = __nv_bfloat162(l0, l1);
                    }
                }
            }
        }
    }
}

// ---------------------------------------------------------------------------
// Tensor-core causal flash attention (R14 structure + per-warp chunk skip +
// ex2-fused softmax). AK=64, 2 CTAs/SM.
// QK^T: bf16x3 mma16 (Q/K pre-split hi/lo). P*V: 1xTF32.
// ---------------------------------------------------------------------------
#define AQ 128
#define AK 64
#define QKW 36                 // Q/K row stride in 32-bit words (72 bf16)
#define VSTR 72                // V row stride in floats
#define QW_F  (AQ*QKW)
#define KW_F  (AK*QKW)
#define VW_F  (AK*VSTR)
#define ATTN_SMEM (27648*4)

__global__ __launch_bounds__(256, 2) void attn_tc(const __nv_bfloat16* __restrict__ qh,
                                                  const __nv_bfloat16* __restrict__ ql,
                                                  const __nv_bfloat16* __restrict__ kh,
                                                  const __nv_bfloat16* __restrict__ kl,
                                                  const float* __restrict__ v,
                                                  __nv_bfloat16* __restrict__ oh,
                                                  __nv_bfloat16* __restrict__ ol) {
    extern __shared__ uint32_t smw[];
    uint32_t* QhS = smw;                    // [AQ][QKW]
    uint32_t* QlS = QhS + QW_F;
    uint32_t* KW  = QlS + QW_F;             // [2][Kh|Kl][AK][QKW]
    float*    VS  = (float*)(KW + 2*2*KW_F);// [2][AK][VSTR]

    const int bh = blockIdx.y;
    const int qi = (int)gridDim.x - 1 - (int)blockIdx.x;
    const int q0 = qi * AQ;
    const int tid = threadIdx.x;
    const int lane = tid & 31;
    const int warp = tid >> 5;
    const int g = lane >> 2, t = lane & 3;
    const int wm = warp * 16;

    const __nv_bfloat16* qhb = qh + (size_t)bh * NS * NDK;
    const __nv_bfloat16* qlb = ql + (size_t)bh * NS * NDK;
    const __nv_bfloat16* khb = kh + (size_t)bh * NS * NDK;
    const __nv_bfloat16* klb = kl + (size_t)bh * NS * NDK;
    const float*         vbp = v  + (size_t)bh * NS * NDK;

    // stage Q hi/lo tiles (128 rows x 128 B each)
    for (int i = tid; i < AQ*8; i += 256) {
        int r = i >> 3, c = i & 7;              // c = 16B chunk
        uint4 xh4 = *reinterpret_cast<const uint4*>(
            (const char*)qhb + (size_t)(q0+r)*128 + c*16);
        uint4 xl4 = *reinterpret_cast<const uint4*>(
            (const char*)qlb + (size_t)(q0+r)*128 + c*16);
        *reinterpret_cast<uint4*>(&QhS[r*QKW + c*4]) = xh4;
        *reinterpret_cast<uint4*>(&QlS[r*QKW + c*4]) = xl4;
    }

    auto issueKV = [&](int buf, int k0) {
        uint32_t* KhD = KW + buf*2*KW_F;
        uint32_t* KlD = KhD + KW_F;
        float*    VD  = VS + buf*VW_F;
        #pragma unroll
        for (int it = 0; it < 2; it++) {
            int i = tid + it*256;
            int r = i >> 3, c = i & 7;
            cpa16(smem_u32(&KhD[r*QKW + c*4]),
                  (const char*)khb + (size_t)(k0+r)*128 + c*16);
            cpa16(smem_u32(&KlD[r*QKW + c*4]),
                  (const char*)klb + (size_t)(k0+r)*128 + c*16);
        }
        #pragma unroll
        for (int it = 0; it < 4; it++) {
            int i = tid + it*256;
            int r = i >> 4, c = (i & 15) << 2;
            cpa16(smem_u32(&VD[r*VSTR + c]), &vbp[(size_t)(k0+r)*NDK + c]);
        }
        asm volatile("cp.async.commit_group;");
    };

    float oacc[8][4] = {};
    float sacc[8][4];
    float Lacc[2] = {0.f, 0.f};

    const int nch = q0/AK + 2;
    issueKV(0, 0);

    const float EC1 = 0.18033688011112042f;    //  0.125 * log2(e)
    const float EC2 = -14.426950408889634f;    // -10    * log2(e)

    for (int ch = 0; ch < nch; ch++) {
        const int buf = ch & 1;
        const int k0 = ch * AK;
        asm volatile("cp.async.wait_group 0;");
        __syncthreads();
        if (ch + 1 < nch) issueKV(1 - buf, (ch + 1) * AK);

        // per-warp skip: chunk fully masked for this warp's 16 q-rows
        if (k0 > q0 + wm + 15) continue;

        const uint32_t* KhS = KW + buf*2*KW_F;
        const uint32_t* KlS = KhS + KW_F;
        const float*    Vsb = VS + buf*VW_F;

        // S = Q K^T, bf16x3 (pure LDS + HMMA)
        #pragma unroll
        for (int i = 0; i < 8; i++)
            #pragma unroll
            for (int j = 0; j < 4; j++) sacc[i][j] = 0.f;
        #pragma unroll
        for (int ks = 0; ks < 4; ks++) {
            const int kb = ks*8;
            uint32_t qhf[4], qlf[4];
            const int r0 = (wm + g)*QKW, r8 = (wm + g + 8)*QKW;
            qhf[0] = QhS[r0 + kb + t];
            qhf[1] = QhS[r8 + kb + t];
            qhf[2] = QhS[r0 + kb + t + 4];
            qhf[3] = QhS[r8 + kb + t + 4];
            qlf[0] = QlS[r0 + kb + t];
            qlf[1] = QlS[r8 + kb + t];
            qlf[2] = QlS[r0 + kb + t + 4];
            qlf[3] = QlS[r8 + kb + t + 4];
            #pragma unroll
            for (int nt = 0; nt < 8; nt++) {
                const int rb = (nt*8 + g)*QKW;
                uint32_t khf[2], klf[2];
                khf[0] = KhS[rb + kb + t];
                khf[1] = KhS[rb + kb + t + 4];
                klf[0] = KlS[rb + kb + t];
                klf[1] = KlS[rb + kb + t + 4];
                mma16(sacc[nt], qlf, khf);
                mma16(sacc[nt], qhf, klf);
                mma16(sacc[nt], qhf, khf);
            }
        }

        // softmax weights: clamp, fused scale+shift, ex2; mask; tf32 round
        const bool need_mask = (k0 + AK - 1 > q0 + wm);
        #pragma unroll
        for (int nt = 0; nt < 8; nt++) {
            #pragma unroll
            for (int e2 = 0; e2 < 4; e2++) {
                const int col = nt*8 + 2*t + (e2 & 1);
                const int rq  = q0 + wm + g + 8*(e2 >> 1);
                float sarg = fminf(fmaxf(sacc[nt][e2], -80.f), 80.f);
                float p;
                asm("ex2.approx.f32 %0, %1;" : "=f"(p) : "f"(fmaf(sarg, EC1, EC2)));
                if (need_mask && (k0 + col > rq)) p = 0.f;
                p = tf32r(p);
                sacc[nt][e2] = p;
                Lacc[e2 >> 1] += p;
            }
        }

        // O += P * V (1xTF32): P frags via in-warp shuffles
        #pragma unroll
        for (int ks = 0; ks < 8; ks++) {
            const int kp = ks*8;
            const int srcA = (g << 2) + (t >> 1);
            const int srcB = srcA + 2;
            float v00 = __shfl_sync(0xffffffffu, sacc[ks][0], srcA);
            float v01 = __shfl_sync(0xffffffffu, sacc[ks][1], srcA);
            float v10 = __shfl_sync(0xffffffffu, sacc[ks][2], srcA);
            float v11 = __shfl_sync(0xffffffffu, sacc[ks][3], srcA);
            float w00 = __shfl_sync(0xffffffffu, sacc[ks][0], srcB);
            float w01 = __shfl_sync(0xffffffffu, sacc[ks][1], srcB);
            float w10 = __shfl_sync(0xffffffffu, sacc[ks][2], srcB);
            float w11 = __shfl_sync(0xffffffffu, sacc[ks][3], srcB);
            const bool odd = (t & 1);
            uint32_t pa[4];
            pa[0] = __float_as_uint(odd ? v01 : v00);
            pa[1] = __float_as_uint(odd ? v11 : v10);
            pa[2] = __float_as_uint(odd ? w01 : w00);
            pa[3] = __float_as_uint(odd ? w11 : w10);
            #pragma unroll
            for (int nt = 0; nt < 8; nt++) {
                uint32_t vb2[2];
                vb2[0] = __float_as_uint(Vsb[(kp + t    )*VSTR + nt*8 + g]);
                vb2[1] = __float_as_uint(Vsb[(kp + t + 4)*VSTR + nt*8 + g]);
                mma8(oacc[nt], pa, vb2);
            }
        }
    }

    float l0 = Lacc[0];
    l0 += __shfl_xor_sync(0xffffffffu, l0, 1);
    l0 += __shfl_xor_sync(0xffffffffu, l0, 2);
    float l1 = Lacc[1];
    l1 += __shfl_xor_sync(0xffffffffu, l1, 1);
    l1 += __shfl_xor_sync(0xffffffffu, l1, 2);
    const float inv0 = 1.0f / l0;
    const float inv1 = 1.0f / l1;

    // write att split to blocked bf16 layout: kk = h*64 + cc
    const int b = bh >> 4, h = bh & 15;
    const int tok0 = b*NS + q0 + wm + g;
    const int tok1 = tok0 + 8;
    #pragma unroll
    for (int nt = 0; nt < 8; nt++) {
        const int cc = nt*8 + 2*t;
        const int kk = h*64 + cc;
        const size_t o0 = ((size_t)(kk >> 5)*NTOK + tok0)*32 + (kk & 31);
        const size_t o1 = ((size_t)(kk >> 5)*NTOK + tok1)*32 + (kk & 31);
        __nv_bfloat16 h0, lo0, h1, lo1;
        splitbf(oacc[nt][0]*inv0, h0, lo0);
        splitbf(oacc[nt][1]*inv0, h1, lo1);
        *reinterpret_cast<__nv_bfloat162*>(&oh[o0]) = __nv_bfloat162(h0, h1);
        *reinterpret_cast<__nv_bfloat162*>(&ol[o0]) = __nv_bfloat162(lo0, lo1);
        splitbf(oacc[nt][2]*inv1, h0, lo0);
        splitbf(oacc[nt][3]*inv1, h1, lo1);
        *reinterpret_cast<__nv_bfloat162*>(&oh[o1]) = __nv_bfloat162(h0, h1);
        *reinterpret_cast<__nv_bfloat162*>(&ol[o1]) = __nv_bfloat162(lo0, lo1);
    }
}

// ---------------------------------------------------------------------------
// Launch (graph-capturable: kernel launches only)
// ---------------------------------------------------------------------------
extern "C" void kernel_launch(void* const* d_in, const int* in_sizes, int n_in,
                              void* d_out, int out_size) {
    const float* x  = (const float*)d_in[0];
    const float* Wq = (const float*)d_in[1];
    const float* Wk = (const float*)d_in[2];
    const float* Wv = (const float*)d_in[3];
    const float* Wo = (const float*)d_in[4];
    float* out = (float*)d_out;

    float *vp;
    __nv_bfloat16 *qhp, *qlp, *khp, *klp, *xh, *xl, *wh, *wl;
    cudaGetSymbolAddress((void**)&qhp, g_qh);
    cudaGetSymbolAddress((void**)&qlp, g_ql);
    cudaGetSymbolAddress((void**)&khp, g_kh);
    cudaGetSymbolAddress((void**)&klp, g_kl);
    cudaGetSymbolAddress((void**)&vp,  g_v);
    cudaGetSymbolAddress((void**)&xh,  g_xh);
    cudaGetSymbolAddress((void**)&xl,  g_xl);
    cudaGetSymbolAddress((void**)&wh,  g_wh);
    cudaGetSymbolAddress((void**)&wl,  g_wl);

    cudaFuncSetAttribute(attn_tc,    cudaFuncAttributeMaxDynamicSharedMemorySize, ATTN_SMEM);
    cudaFuncSetAttribute(gemm_bf<0>, cudaFuncAttributeMaxDynamicSharedMemorySize, GEMM_SMEM);
    cudaFuncSetAttribute(gemm_bf<1>, cudaFuncAttributeMaxDynamicSharedMemorySize, GEMM_SMEM);

    prep_rope<<<NS*32/256, 256>>>();
    prep_x<<<NTOK*ND/4/256, 256>>>(x, xh, xl);
    prep_w<<<dim3(ND*ND/4/256, 4), 256>>>(Wq, Wk, Wv, Wo, wh, wl);

    gemm_bf<1><<<dim3(ND/128, NTOK/128, 3), 256, GEMM_SMEM>>>(
        xh, xl, wh, wl, qhp, qlp, khp, klp, vp, nullptr);

    attn_tc<<<dim3(NS/AQ, NB*NH), 256, ATTN_SMEM>>>(qhp, qlp, khp, klp, vp, xh, xl);

    gemm_bf<0><<<dim3(ND/128, NTOK/128, 1), 256, GEMM_SMEM>>>(
        xh, xl, wh, wl, nullptr, nullptr, nullptr, nullptr, nullptr, out);
}